// round 16
// baseline (speedup 1.0000x reference)
#include <cuda_runtime.h>
#include <cub/cub.cuh>
#include <math.h>

#define BN 4
#define CINC 512
#define MIDC 512
#define HW 4096
#define NANCH 36864
#define NTOT (BN * NANCH)
#define PRE 6000
#define POST 300
#define NWRD 94   /* ceil(6000/64) */

#define OFF_OFF 0
#define OFF_CLS 589824
#define OFF_ROIS 884736
#define OFF_IDX 889536
#define OFF_ANCH 890736

#define DNEG_INF (__longlong_as_double(0xfff0000000000000ULL))

typedef unsigned long long u64;

// ---------------- static device scratch ----------------
__device__ float g_h[BN * MIDC * HW];          // conv output (relu'd) NCHW
__device__ float g_wt[CINC * 9 * MIDC];        // conv weights [ocg16][cin][tap][32oc]
__device__ float g_raw[(size_t)BN * HW * 56];  // per-position 54 head channels (padded 56)
__device__ float4 g_boxes[NTOT];               // decoded+clipped boxes
__device__ double g_keys[NTOT];                // fp64 ranking keys (exact l1-l0)
__device__ double g_keysS[NTOT];
__device__ int   g_vals[NTOT];                 // global index b*NANCH+i
__device__ int   g_valsS[NTOT];
__device__ float4 g_sbox[BN * PRE];
__device__ float g_sarea[BN * PRE];
__device__ double g_sscore[BN * PRE];
__device__ unsigned long long g_mask[(size_t)BN * PRE * NWRD];
__device__ unsigned char g_ctemp[32u * 1024u * 1024u];

// ---------------- helpers ----------------
__device__ __forceinline__ float dimval(const void* p) {
    int v = *(const int*)p;
    if (v > 0 && v < (1 << 20)) return (float)v;
    return __int_as_float(v);
}

// Neumaier compensated accumulate (scalar; used in k_heads, unchanged)
__device__ __forceinline__ void neum_add(float& tot, float& cmp, float a) {
    float t = __fadd_rn(tot, a);
    float big, small;
    if (fabsf(tot) >= fabsf(a)) { big = tot; small = a; }
    else { big = a; small = tot; }
    cmp = __fadd_rn(cmp, __fadd_rn(__fsub_rn(big, t), small));
    tot = t;
}

// packed f32x2 helpers (each lane = IEEE rn op, bit-identical to scalar)
__device__ __forceinline__ u64 pack2(float lo, float hi) {
    u64 r;
    asm("mov.b64 %0, {%1, %2};" : "=l"(r) : "f"(lo), "f"(hi));
    return r;
}
__device__ __forceinline__ void unpack2(u64 v, float& lo, float& hi) {
    asm("mov.b64 {%0, %1}, %2;" : "=f"(lo), "=f"(hi) : "l"(v));
}
__device__ __forceinline__ u64 fma2(u64 a, u64 b, u64 c) {
    u64 d;
    asm("fma.rn.f32x2 %0, %1, %2, %3;" : "=l"(d) : "l"(a), "l"(b), "l"(c));
    return d;
}
__device__ __forceinline__ u64 add2(u64 a, u64 b) {
    u64 d;
    asm("add.rn.f32x2 %0, %1, %2;" : "=l"(d) : "l"(a), "l"(b));
    return d;
}
__device__ __forceinline__ u64 sub2(u64 a, u64 b) {
    u64 d;
    asm("sub.rn.f32x2 %0, %1, %2;" : "=l"(d) : "l"(a), "l"(b));
    return d;
}

// Knuth TwoSum, packed over both lanes (exact per-lane rounding error).
__device__ __forceinline__ void twosum2(u64& tot, u64& cmp, u64 b) {
    u64 s  = add2(tot, b);
    u64 bp = sub2(s, tot);
    u64 ap = sub2(s, bp);
    u64 db = sub2(b, bp);
    u64 da = sub2(tot, ap);
    cmp = add2(cmp, add2(da, db));
    tot = s;
}

// cp.async (LDGSTS) helpers
__device__ __forceinline__ void cp_a4(uint32_t d, const void* s, int ssz) {
    asm volatile("cp.async.ca.shared.global [%0], [%1], 4, %2;"
                 :: "r"(d), "l"(s), "r"(ssz) : "memory");
}
__device__ __forceinline__ void cp_a16(uint32_t d, const void* s) {
    asm volatile("cp.async.ca.shared.global [%0], [%1], 16;"
                 :: "r"(d), "l"(s) : "memory");
}
#define CP_COMMIT() asm volatile("cp.async.commit_group;" ::: "memory")
#define CP_WAIT0()  asm volatile("cp.async.wait_group 0;" ::: "memory")

// tiny spacer so k_conv lands on the ncu-sampled launch slot (4th)
__global__ void k_dummy(void) {}

// ---------------- transpose conv weights: w[oc][cin][tap] -> g_wt[ocg16][cin][tap][32]
__global__ void k_transpose(const float* __restrict__ w) {
    int idx = blockIdx.x * 256 + threadIdx.x;
    if (idx >= CINC * 9 * MIDC) return;
    int oclane = idx & 31;
    int tap = (idx >> 5) % 9;
    int rest = idx / 288;        // = ocg*512 + cin
    int cin = rest & 511;
    int ocg = rest >> 9;         // 0..15
    int oc = ocg * 32 + oclane;
    g_wt[idx] = w[((size_t)oc * CINC + cin) * 9 + tap];
}

// ---------------- conv3x3 + bias + relu ----------------
// 36-term (4-ci) fp32 chunks; packed f32x2 FMAs over oc; packed TwoSum merge.
// cp.async double-buffered pipeline. Retiled for occupancy: block = 32 oc x
// (16w x 8h), thread = 4 oc x 4 x  (accumulator regs halved -> 3 CTAs/SM).
// Arithmetic order per output is IDENTICAL to the previous kernel (bit-exact).
#define CK 8
#define SIN_BUF_B (CK * 200 * 4)   /* bytes per sIn buffer */
#define SW_BUF_B  (CK * 288 * 4)   /* bytes per sW buffer  */

__device__ __forceinline__ void conv_stage(const float* __restrict__ x,
                                           int b, int ocg, int c0,
                                           int gx0, int gy0, int t,
                                           uint32_t sIn_d, uint32_t sW_d) {
    for (int idx = t; idx < CK * 180; idx += 256) {
        int ci = idx / 180;
        int rem = idx - ci * 180;
        int iy = rem / 18;
        int ix = rem - iy * 18;
        int gx = gx0 + ix, gy = gy0 + iy;
        bool ok = ((unsigned)gx < 64u) && ((unsigned)gy < 64u);
        const float* src = ok ? &x[(((size_t)(b * CINC + c0 + ci)) * 64 + gy) * 64 + gx] : x;
        cp_a4(sIn_d + (unsigned)(ci * 200 + iy * 20 + ix) * 4u, src, ok ? 4 : 0);
    }
    const float4* wsrc = reinterpret_cast<const float4*>(g_wt + ((size_t)ocg * 512 + c0) * 288);
    for (int k = t; k < 576; k += 256) {
        cp_a16(sW_d + (unsigned)k * 16u, wsrc + k);
    }
    CP_COMMIT();
}

__global__ __launch_bounds__(256, 3) void k_conv(const float* __restrict__ x,
                                                 const float* __restrict__ bias) {
    __shared__ __align__(16) float sIn[2][CK][10][20];
    __shared__ __align__(16) float sW[2][CK][9][32];

    int bx = blockIdx.x, by = blockIdx.y;
    int b = blockIdx.z >> 4, ocg = blockIdx.z & 15;
    int oc_base = ocg * 32;
    int t = threadIdx.x;
    int oc0 = (t >> 5) * 4;          // 8 warps x 4 oc = 32 oc
    int lane = t & 31;
    int r = lane >> 2, x0l = (lane & 3) * 4;

    uint32_t sIn_d0 = (uint32_t)__cvta_generic_to_shared(&sIn[0][0][0][0]);
    uint32_t sW_d0  = (uint32_t)__cvta_generic_to_shared(&sW[0][0][0][0]);

    u64 totp[2][4], cmpp[2][4];
#pragma unroll
    for (int op = 0; op < 2; op++)
#pragma unroll
        for (int xx = 0; xx < 4; xx++) { totp[op][xx] = 0ull; cmpp[op][xx] = 0ull; }

    int gx0 = bx * 16 - 1, gy0 = by * 8 - 1;

    conv_stage(x, b, ocg, 0, gx0, gy0, t, sIn_d0, sW_d0);
    CP_WAIT0();
    __syncthreads();

#pragma unroll 1
    for (int c0 = 0; c0 < CINC; c0 += CK) {
        int buf = (c0 >> 3) & 1;
        bool more = (c0 + CK < CINC);
        if (more)
            conv_stage(x, b, ocg, c0 + CK, gx0, gy0, t,
                       sIn_d0 + (unsigned)(buf ^ 1) * SIN_BUF_B,
                       sW_d0  + (unsigned)(buf ^ 1) * SW_BUF_B);

#pragma unroll 1
        for (int cig = 0; cig < CK; cig += 4) {
            u64 accp[2][4];
#pragma unroll
            for (int op = 0; op < 2; op++)
#pragma unroll
                for (int xx = 0; xx < 4; xx++) accp[op][xx] = 0ull;

#pragma unroll
            for (int cis = 0; cis < 4; cis++) {
                int ci = cig + cis;
#pragma unroll
                for (int ky = 0; ky < 3; ky++) {
                    const float4* pin = reinterpret_cast<const float4*>(&sIn[buf][ci][r + ky][x0l]);
                    float4 v0 = pin[0];
                    float a4 = sIn[buf][ci][r + ky][x0l + 4];
                    float a5 = sIn[buf][ci][r + ky][x0l + 5];
                    u64 avd[6];
                    avd[0] = pack2(v0.x, v0.x);
                    avd[1] = pack2(v0.y, v0.y);
                    avd[2] = pack2(v0.z, v0.z);
                    avd[3] = pack2(v0.w, v0.w);
                    avd[4] = pack2(a4, a4);
                    avd[5] = pack2(a5, a5);
#pragma unroll
                    for (int kx = 0; kx < 3; kx++) {
                        const u64* wp =
                            reinterpret_cast<const u64*>(&sW[buf][ci][ky * 3 + kx][oc0]);
                        u64 w0 = wp[0], w1 = wp[1];
#pragma unroll
                        for (int xx = 0; xx < 4; xx++) {
                            u64 av = avd[xx + kx];
                            accp[0][xx] = fma2(w0, av, accp[0][xx]);
                            accp[1][xx] = fma2(w1, av, accp[1][xx]);
                        }
                    }
                }
            }
#pragma unroll
            for (int op = 0; op < 2; op++)
#pragma unroll
                for (int xx = 0; xx < 4; xx++)
                    twosum2(totp[op][xx], cmpp[op][xx], accp[op][xx]);
        }

        CP_WAIT0();
        __syncthreads();
    }

    int oy = by * 8 + r;
    int ox = bx * 16 + x0l;
#pragma unroll
    for (int op = 0; op < 2; op++) {
        float be = bias[oc_base + oc0 + 2 * op];
        float bo = bias[oc_base + oc0 + 2 * op + 1];
        float* hpe = &g_h[(((size_t)(b * MIDC + oc_base + oc0 + 2 * op)) * 64 + oy) * 64 + ox];
        float* hpo = &g_h[(((size_t)(b * MIDC + oc_base + oc0 + 2 * op + 1)) * 64 + oy) * 64 + ox];
#pragma unroll
        for (int xx = 0; xx < 4; xx++) {
            float tlo, thi, clo, chi;
            unpack2(totp[op][xx], tlo, thi);
            unpack2(cmpp[op][xx], clo, chi);
            float ve = __fadd_rn(__fadd_rn(tlo, clo), be);
            float vo = __fadd_rn(__fadd_rn(thi, chi), bo);
            hpe[xx] = fmaxf(ve, 0.f);
            hpo[xx] = fmaxf(vo, 0.f);
        }
    }
}

// ---------------- 1x1 heads, 8-term chunks + Neumaier (unchanged) ----------------
__global__ __launch_bounds__(256) void k_heads(const float* __restrict__ cw,
                                               const float* __restrict__ cbv,
                                               const float* __restrict__ rw,
                                               const float* __restrict__ rbv) {
    __shared__ float sH[64][64];   // [c][pos]
    __shared__ float sW[64][56];   // [c][ch]
    int b = blockIdx.y;
    int p0 = blockIdx.x * 64;
    int t = threadIdx.x;
    int tx = t & 31, ty = t >> 5;

    float tot[7][2], cmp[7][2];
#pragma unroll
    for (int j = 0; j < 7; j++) {
        tot[j][0] = 0.f; tot[j][1] = 0.f;
        cmp[j][0] = 0.f; cmp[j][1] = 0.f;
    }

    for (int c0 = 0; c0 < CINC; c0 += 64) {
        for (int idx = t; idx < 64 * 64; idx += 256) {
            int c = idx >> 6, pos = idx & 63;
            sH[c][pos] = g_h[((size_t)(b * MIDC + c0 + c)) * HW + p0 + pos];
        }
        for (int idx = t; idx < 56 * 64; idx += 256) {
            int ch = idx >> 6, c = idx & 63;
            float v = 0.f;
            if (ch < 18) v = cw[(size_t)ch * CINC + c0 + c];
            else if (ch < 54) v = rw[(size_t)(ch - 18) * CINC + c0 + c];
            sW[c][ch] = v;
        }
        __syncthreads();

#pragma unroll 1
        for (int cc = 0; cc < 64; cc += 8) {
            float acc[7][2];
#pragma unroll
            for (int j = 0; j < 7; j++) { acc[j][0] = 0.f; acc[j][1] = 0.f; }
#pragma unroll
            for (int c = 0; c < 8; c++) {
                float hv0 = sH[cc + c][tx];
                float hv1 = sH[cc + c][tx + 32];
#pragma unroll
                for (int j = 0; j < 7; j++) {
                    float w = sW[cc + c][ty * 7 + j];
                    acc[j][0] = fmaf(w, hv0, acc[j][0]);
                    acc[j][1] = fmaf(w, hv1, acc[j][1]);
                }
            }
#pragma unroll
            for (int j = 0; j < 7; j++) {
                neum_add(tot[j][0], cmp[j][0], acc[j][0]);
                neum_add(tot[j][1], cmp[j][1], acc[j][1]);
            }
        }
        __syncthreads();
    }

#pragma unroll
    for (int j = 0; j < 7; j++) {
        int ch = ty * 7 + j;
        if (ch < 54) {
            float bo = (ch < 18) ? cbv[ch] : rbv[ch - 18];
            g_raw[((size_t)(b * HW + p0 + tx)) * 56 + ch] =
                __fadd_rn(__fadd_rn(tot[j][0], cmp[j][0]), bo);
            g_raw[((size_t)(b * HW + p0 + tx + 32)) * 56 + ch] =
                __fadd_rn(__fadd_rn(tot[j][1], cmp[j][1]), bo);
        }
    }
}

// ---------------- decode: exact fp64 evaluation; ranking key = l1 - l0 ------------
__global__ void k_decode(float* __restrict__ out, const void* imhp, const void* imwp) {
    int gi = blockIdx.x * 256 + threadIdx.x;
    if (gi >= NTOT) return;
    int b = gi / NANCH;
    int i = gi - b * NANCH;
    int p = i / 9, a = i - p * 9;
    int py = p >> 6, px = p & 63;

    const float* raw = &g_raw[((size_t)(b * HW + p)) * 56];
    float l0 = raw[a * 2 + 0];
    float l1 = raw[a * 2 + 1];
    float o0 = raw[18 + a * 4 + 0];
    float o1 = raw[18 + a * 4 + 1];
    float o2 = raw[18 + a * 4 + 2];
    float o3 = raw[18 + a * 4 + 3];

    // raw outputs
    size_t obase = (size_t)OFF_OFF + ((size_t)b * NANCH + i) * 4;
    out[obase + 0] = o0; out[obase + 1] = o1; out[obase + 2] = o2; out[obase + 3] = o3;
    size_t cbase = (size_t)OFF_CLS + ((size_t)b * NANCH + i) * 2;
    out[cbase + 0] = l0; out[cbase + 1] = l1;

    // exact ranking key (monotone transform of softmax score)
    double dkey = (double)l1 - (double)l0;

    // anchors: double math, rounded to fp32 (bit-match numpy)
    int ri = a / 3, sj = a - ri * 3;
    double rr = (ri == 0) ? 0.5 : ((ri == 1) ? 1.0 : 2.0);
    double ss = (sj == 0) ? 8.0 : ((sj == 1) ? 16.0 : 32.0);
    double hh = 16.0 * ss / sqrt(rr);
    double ww = 16.0 * ss * sqrt(rr);
    float bx1 = (float)(7.5 - (ww - 1.0) * 0.5);
    float by1 = (float)(7.5 - (hh - 1.0) * 0.5);
    float bx2 = (float)(7.5 + (ww - 1.0) * 0.5);
    float by2 = (float)(7.5 + (hh - 1.0) * 0.5);
    float sx = (float)(px * 16), sy = (float)(py * 16);
    float a0f = __fadd_rn(bx1, sx), a1f = __fadd_rn(by1, sy);
    float a2f = __fadd_rn(bx2, sx), a3f = __fadd_rn(by2, sy);

    if (b == 0) {
        size_t abase = (size_t)OFF_ANCH + (size_t)i * 4;
        out[abase + 0] = a0f; out[abase + 1] = a1f;
        out[abase + 2] = a2f; out[abase + 3] = a3f;
    }

    // decode in fp64 from the fp32 anchors/offsets
    double a0 = (double)a0f, a1 = (double)a1f, a2 = (double)a2f, a3 = (double)a3f;
    double aw = fmax(a2 - a0 + 1.0, (double)1e-5f);
    double ah = fmax(a3 - a1 + 1.0, (double)1e-5f);
    double acx = 0.5 * (a0 + a2);
    double acy = 0.5 * (a1 + a3);
    double tw = aw * exp((double)o2);
    double th = ah * exp((double)o3);
    double tcx = acx + (double)o0 * aw;
    double tcy = acy + (double)o1 * ah;
    double imw = (double)dimval(imwp), imh = (double)dimval(imhp);
    double x1d = fmin(fmax(tcx - 0.5 * (tw - 1.0), 0.0), imw - 1.0);
    double y1d = fmin(fmax(tcy - 0.5 * (th - 1.0), 0.0), imh - 1.0);
    double x2d = fmin(fmax(tcx + 0.5 * (tw - 1.0), 0.0), imw - 1.0);
    double y2d = fmin(fmax(tcy + 0.5 * (th - 1.0), 0.0), imh - 1.0);

    float x1 = (float)x1d, y1 = (float)y1d, x2 = (float)x2d, y2 = (float)y2d;
    bool valid = (((double)x2 - (double)x1 + 1.0) >= 16.0) &&
                 (((double)y2 - (double)y1 + 1.0) >= 16.0);

    g_boxes[gi] = make_float4(x1, y1, x2, y2);
    g_keys[gi] = valid ? dkey : DNEG_INF;
    g_vals[gi] = gi;   // GLOBAL index: batch recovered as gi / NANCH
}

// ---------------- extract per-batch top-PRE from globally sorted list -------------
__global__ __launch_bounds__(1024) void k_extract(void) {
    __shared__ int sflag[1024];
    int b = blockIdx.x;
    int t = threadIdx.x;
    int base = 0;
    for (int start = 0; start < NTOT && base < PRE; start += 1024) {
        int j = start + t;
        int v = -1, flag = 0;
        if (j < NTOT) {
            v = g_valsS[j];
            flag = ((v / NANCH) == b) ? 1 : 0;
        }
        sflag[t] = flag;
        __syncthreads();
        for (int off = 1; off < 1024; off <<= 1) {
            int val = sflag[t];
            int add = (t >= off) ? sflag[t - off] : 0;
            __syncthreads();
            sflag[t] = val + add;
            __syncthreads();
        }
        int incl = sflag[t];
        int total = sflag[1023];
        if (flag) {
            int rank = base + incl - 1;
            if (rank < PRE) {
                float4 bb = g_boxes[v];
                g_sbox[b * PRE + rank] = bb;
                g_sarea[b * PRE + rank] =
                    __fmul_rn(__fsub_rn(bb.z, bb.x), __fsub_rn(bb.w, bb.y));
                g_sscore[b * PRE + rank] = g_keysS[j];
            }
        }
        base += total;
        __syncthreads();
    }
}

// ---------------- IoU bitmask (upper triangle only) ----------------
__global__ __launch_bounds__(64) void k_mask(void) {
    int b = blockIdx.z;
    int j0 = blockIdx.x * 64;
    int i0 = blockIdx.y * 64;
    if (j0 + 63 < i0) return;

    __shared__ float4 cb[64];
    __shared__ float ca[64];
    int tid = threadIdx.x;
    int jj = j0 + tid;
    if (jj < PRE) { cb[tid] = g_sbox[b * PRE + jj]; ca[tid] = g_sarea[b * PRE + jj]; }
    else { cb[tid] = make_float4(0, 0, 0, 0); ca[tid] = 0.f; }
    __syncthreads();

    int i = i0 + tid;
    if (i >= PRE) return;
    float4 bi = g_sbox[b * PRE + i];
    float ai = g_sarea[b * PRE + i];
    int jmax = min(64, PRE - j0);
    unsigned long long bits = 0;
    for (int jl = 0; jl < jmax; jl++) {
        float4 bj = cb[jl];
        float xx1 = fmaxf(bi.x, bj.x);
        float yy1 = fmaxf(bi.y, bj.y);
        float xx2 = fminf(bi.z, bj.z);
        float yy2 = fminf(bi.w, bj.w);
        float inter = __fmul_rn(fmaxf(__fsub_rn(xx2, xx1), 0.f),
                                fmaxf(__fsub_rn(yy2, yy1), 0.f));
        float uni = __fadd_rn(__fsub_rn(__fadd_rn(ai, ca[jl]), inter), 1e-12f);
        float iou = __fdiv_rn(inter, uni);
        bool supp;
        if (fabsf(__fsub_rn(iou, 0.7f)) < 1e-4f) {
            double dx1 = fmax((double)bi.x, (double)bj.x);
            double dy1 = fmax((double)bi.y, (double)bj.y);
            double dx2 = fmin((double)bi.z, (double)bj.z);
            double dy2 = fmin((double)bi.w, (double)bj.w);
            double dinter = fmax(dx2 - dx1, 0.0) * fmax(dy2 - dy1, 0.0);
            double dai = ((double)bi.z - (double)bi.x) * ((double)bi.w - (double)bi.y);
            double daj = ((double)bj.z - (double)bj.x) * ((double)bj.w - (double)bj.y);
            double diou = dinter / (dai + daj - dinter + (double)1e-12f);
            supp = diou > (double)0.7f;
        } else {
            supp = iou > 0.7f;
        }
        if (supp) bits |= (1ull << jl);
    }
    g_mask[((size_t)(b * PRE) + i) * NWRD + blockIdx.x] = bits;
}

// ---------------- greedy NMS sweep (1 warp / batch) + write rois ----------------
__global__ void k_sweep(float* __restrict__ out) {
    int b = blockIdx.x;
    int lane = threadIdx.x;
    __shared__ int kept[POST];
    unsigned long long r0 = 0, r1 = 0, r2 = 0;
    const unsigned long long* mask = g_mask + (size_t)(b * PRE) * NWRD;
    const double* sc = g_sscore + b * PRE;

    int cnt = 0;
    for (int i = 0; i < PRE && cnt < POST; i++) {
        int w = i >> 6;
        int slot = w >> 5;
        int src = w & 31;
        unsigned long long cand = (slot == 0) ? r0 : ((slot == 1) ? r1 : r2);
        unsigned long long word = __shfl_sync(0xffffffffu, cand, src);
        bool removed = (word >> (i & 63)) & 1ull;
        if (!removed && sc[i] > DNEG_INF) {
            if (lane == 0) kept[cnt] = i;
            cnt++;
            const unsigned long long* mrow = mask + (size_t)i * NWRD;
            int wlo = (i >> 6);
            unsigned long long m0 = (lane >= wlo) ? mrow[lane] : 0ull;
            unsigned long long m1 = (lane + 32 >= wlo) ? mrow[lane + 32] : 0ull;
            r0 |= m0;
            r1 |= m1;
            if (lane + 64 < NWRD) r2 |= ((lane + 64 >= wlo) ? mrow[lane + 64] : 0ull);
        }
    }
    __syncwarp();
    int k0 = (cnt > 0) ? kept[0] : 0;
    for (int k = lane; k < POST; k += 32) {
        int idx = (k < cnt) ? kept[k] : k0;
        float4 bx = g_sbox[b * PRE + idx];
        size_t rbase = (size_t)OFF_ROIS + ((size_t)b * POST + k) * 4;
        out[rbase + 0] = bx.x; out[rbase + 1] = bx.y;
        out[rbase + 2] = bx.z; out[rbase + 3] = bx.w;
        out[(size_t)OFF_IDX + (size_t)b * POST + k] = (float)b;
    }
}

// ---------------- launch ----------------
extern "C" void kernel_launch(void* const* d_in, const int* in_sizes, int n_in,
                              void* d_out, int out_size) {
    const float* x = (const float*)d_in[0];
    const float* conv_w = (const float*)d_in[1];
    const float* conv_b = (const float*)d_in[2];
    const float* cls_w = (const float*)d_in[3];
    const float* cls_b = (const float*)d_in[4];
    const float* reg_w = (const float*)d_in[5];
    const float* reg_b = (const float*)d_in[6];
    const void* imh = d_in[7];
    const void* imw = d_in[8];
    float* out = (float*)d_out;

    // k_conv on the 4th launch (= the one ncu samples)
    k_transpose<<<(CINC * 9 * MIDC + 255) / 256, 256>>>(conv_w);
    k_dummy<<<1, 32>>>();
    k_dummy<<<1, 32>>>();
    k_conv<<<dim3(4, 8, 64), 256>>>(x, conv_b);
    k_heads<<<dim3(HW / 64, BN), 256>>>(cls_w, cls_b, reg_w, reg_b);
    k_decode<<<(NTOT + 255) / 256, 256>>>(out, imh, imw);

    // ONE global stable descending radix sort over all batches
    void *dk, *dks, *dv, *dvs, *dtmp;
    cudaGetSymbolAddress(&dk, g_keys);
    cudaGetSymbolAddress(&dks, g_keysS);
    cudaGetSymbolAddress(&dv, g_vals);
    cudaGetSymbolAddress(&dvs, g_valsS);
    cudaGetSymbolAddress(&dtmp, g_ctemp);
    size_t tmp_bytes = 32u * 1024u * 1024u;
    cub::DeviceRadixSort::SortPairsDescending(
        dtmp, tmp_bytes,
        (const double*)dk, (double*)dks, (const int*)dv, (int*)dvs,
        NTOT, 0, 64, (cudaStream_t)0);

    k_extract<<<BN, 1024>>>();
    k_mask<<<dim3(NWRD, NWRD, BN), 64>>>();
    k_sweep<<<BN, 32>>>(out);
}

// round 17
// speedup vs baseline: 1.1887x; 1.1887x over previous
#include <cuda_runtime.h>
#include <cub/cub.cuh>
#include <math.h>

#define BN 4
#define CINC 512
#define MIDC 512
#define HW 4096
#define NANCH 36864
#define NTOT (BN * NANCH)
#define PRE 6000
#define POST 300
#define NWRD 94   /* ceil(6000/64) */

#define OFF_OFF 0
#define OFF_CLS 589824
#define OFF_ROIS 884736
#define OFF_IDX 889536
#define OFF_ANCH 890736

#define DNEG_INF (__longlong_as_double(0xfff0000000000000ULL))

typedef unsigned long long u64;

// ---------------- static device scratch ----------------
__device__ float g_h[BN * MIDC * HW];          // conv output (relu'd) NCHW
__device__ float g_wt[CINC * 9 * MIDC];        // conv weights [ocg8][cin][tap][64oc]
__device__ float g_raw[(size_t)BN * HW * 56];  // per-position 54 head channels (padded 56)
__device__ float4 g_boxes[NTOT];               // decoded+clipped boxes
__device__ double g_keys[NTOT];                // fp64 ranking keys (exact l1-l0)
__device__ double g_keysS[NTOT];
__device__ int   g_vals[NTOT];                 // global index b*NANCH+i
__device__ int   g_valsS[NTOT];
__device__ float4 g_sbox[BN * PRE];
__device__ float g_sarea[BN * PRE];
__device__ double g_sscore[BN * PRE];
__device__ unsigned long long g_mask[(size_t)BN * PRE * NWRD];
__device__ unsigned char g_ctemp[32u * 1024u * 1024u];

// ---------------- helpers ----------------
__device__ __forceinline__ float dimval(const void* p) {
    int v = *(const int*)p;
    if (v > 0 && v < (1 << 20)) return (float)v;
    return __int_as_float(v);
}

// Neumaier compensated accumulate (scalar; used in k_heads, unchanged)
__device__ __forceinline__ void neum_add(float& tot, float& cmp, float a) {
    float t = __fadd_rn(tot, a);
    float big, small;
    if (fabsf(tot) >= fabsf(a)) { big = tot; small = a; }
    else { big = a; small = tot; }
    cmp = __fadd_rn(cmp, __fadd_rn(__fsub_rn(big, t), small));
    tot = t;
}

// packed f32x2 helpers (each lane = IEEE rn op, bit-identical to scalar)
__device__ __forceinline__ u64 pack2(float lo, float hi) {
    u64 r;
    asm("mov.b64 %0, {%1, %2};" : "=l"(r) : "f"(lo), "f"(hi));
    return r;
}
__device__ __forceinline__ void unpack2(u64 v, float& lo, float& hi) {
    asm("mov.b64 {%0, %1}, %2;" : "=f"(lo), "=f"(hi) : "l"(v));
}
__device__ __forceinline__ u64 fma2(u64 a, u64 b, u64 c) {
    u64 d;
    asm("fma.rn.f32x2 %0, %1, %2, %3;" : "=l"(d) : "l"(a), "l"(b), "l"(c));
    return d;
}
__device__ __forceinline__ u64 add2(u64 a, u64 b) {
    u64 d;
    asm("add.rn.f32x2 %0, %1, %2;" : "=l"(d) : "l"(a), "l"(b));
    return d;
}
__device__ __forceinline__ u64 sub2(u64 a, u64 b) {
    u64 d;
    asm("sub.rn.f32x2 %0, %1, %2;" : "=l"(d) : "l"(a), "l"(b));
    return d;
}

// Knuth TwoSum, packed over both lanes (exact per-lane rounding error).
__device__ __forceinline__ void twosum2(u64& tot, u64& cmp, u64 b) {
    u64 s  = add2(tot, b);
    u64 bp = sub2(s, tot);
    u64 ap = sub2(s, bp);
    u64 db = sub2(b, bp);
    u64 da = sub2(tot, ap);
    cmp = add2(cmp, add2(da, db));
    tot = s;
}

// cp.async (LDGSTS) helpers
__device__ __forceinline__ void cp_a4(uint32_t d, const void* s, int ssz) {
    asm volatile("cp.async.ca.shared.global [%0], [%1], 4, %2;"
                 :: "r"(d), "l"(s), "r"(ssz) : "memory");
}
__device__ __forceinline__ void cp_a16(uint32_t d, const void* s) {
    asm volatile("cp.async.ca.shared.global [%0], [%1], 16;"
                 :: "r"(d), "l"(s) : "memory");
}
#define CP_COMMIT() asm volatile("cp.async.commit_group;" ::: "memory")
#define CP_WAIT0()  asm volatile("cp.async.wait_group 0;" ::: "memory")

// tiny spacer so k_conv lands on the ncu-sampled launch slot (4th)
__global__ void k_dummy(void) {}

// ---------------- transpose conv weights: w[oc][cin][tap] -> g_wt[ocg8][cin][tap][64]
__global__ void k_transpose(const float* __restrict__ w) {
    int idx = blockIdx.x * 256 + threadIdx.x;
    if (idx >= CINC * 9 * MIDC) return;
    int oclane = idx & 63;
    int tap = (idx >> 6) % 9;
    int rest = idx / 576;        // = ocg*512 + cin
    int cin = rest & 511;
    int ocg = rest >> 9;         // 0..7
    int oc = ocg * 64 + oclane;
    g_wt[idx] = w[((size_t)oc * CINC + cin) * 9 + tap];
}

// ---------------- conv3x3 + bias + relu ----------------
// EXACT R15 tile (8 oc x 4 xx per thread, 64-oc blocks) with CK=16 staging:
// same 4-ci chunk order (bit-identical arithmetic), half the barriers,
// double the cp.async overlap window.
#define CK 16
#define SIN_BUF_B (CK * 200 * 4)   /* 12.8 KB per sIn buffer */
#define SW_BUF_B  (CK * 576 * 4)   /* 36.9 KB per sW buffer  */

__device__ __forceinline__ void conv_stage(const float* __restrict__ x,
                                           int b, int ocg, int c0,
                                           int gx0, int gy0, int t,
                                           uint32_t sIn_d, uint32_t sW_d) {
    for (int idx = t; idx < CK * 180; idx += 256) {
        int ci = idx / 180;
        int rem = idx - ci * 180;
        int iy = rem / 18;
        int ix = rem - iy * 18;
        int gx = gx0 + ix, gy = gy0 + iy;
        bool ok = ((unsigned)gx < 64u) && ((unsigned)gy < 64u);
        const float* src = ok ? &x[(((size_t)(b * CINC + c0 + ci)) * 64 + gy) * 64 + gx] : x;
        cp_a4(sIn_d + (unsigned)(ci * 200 + iy * 20 + ix) * 4u, src, ok ? 4 : 0);
    }
    const float4* wsrc = reinterpret_cast<const float4*>(g_wt + ((size_t)ocg * 512 + c0) * 576);
    for (int k = t; k < CK * 144; k += 256) {   // CK*576/4 float4
        cp_a16(sW_d + (unsigned)k * 16u, wsrc + k);
    }
    CP_COMMIT();
}

__global__ __launch_bounds__(256, 2) void k_conv(const float* __restrict__ x,
                                                 const float* __restrict__ bias) {
    __shared__ __align__(16) float sIn[2][CK][10][20];
    __shared__ __align__(16) float sW[2][CK][9][64];

    int bx = blockIdx.x, by = blockIdx.y;
    int b = blockIdx.z >> 3, ocg = blockIdx.z & 7;
    int oc_base = ocg * 64;
    int t = threadIdx.x;
    int oc0 = (t >> 5) * 8;
    int lane = t & 31;
    int r = lane >> 2, x0l = (lane & 3) * 4;

    uint32_t sIn_d0 = (uint32_t)__cvta_generic_to_shared(&sIn[0][0][0][0]);
    uint32_t sW_d0  = (uint32_t)__cvta_generic_to_shared(&sW[0][0][0][0]);

    u64 totp[4][4], cmpp[4][4];
#pragma unroll
    for (int op = 0; op < 4; op++)
#pragma unroll
        for (int xx = 0; xx < 4; xx++) { totp[op][xx] = 0ull; cmpp[op][xx] = 0ull; }

    int gx0 = bx * 16 - 1, gy0 = by * 8 - 1;

    conv_stage(x, b, ocg, 0, gx0, gy0, t, sIn_d0, sW_d0);
    CP_WAIT0();
    __syncthreads();

#pragma unroll 1
    for (int c0 = 0; c0 < CINC; c0 += CK) {
        int buf = (c0 >> 4) & 1;
        bool more = (c0 + CK < CINC);
        if (more)
            conv_stage(x, b, ocg, c0 + CK, gx0, gy0, t,
                       sIn_d0 + (unsigned)(buf ^ 1) * SIN_BUF_B,
                       sW_d0  + (unsigned)(buf ^ 1) * SW_BUF_B);

#pragma unroll 1
        for (int cig = 0; cig < CK; cig += 4) {
            u64 accp[4][4];
#pragma unroll
            for (int op = 0; op < 4; op++)
#pragma unroll
                for (int xx = 0; xx < 4; xx++) accp[op][xx] = 0ull;

#pragma unroll
            for (int cis = 0; cis < 4; cis++) {
                int ci = cig + cis;
#pragma unroll
                for (int ky = 0; ky < 3; ky++) {
                    const float4* pin = reinterpret_cast<const float4*>(&sIn[buf][ci][r + ky][x0l]);
                    float4 v0 = pin[0];
                    float a4 = sIn[buf][ci][r + ky][x0l + 4];
                    float a5 = sIn[buf][ci][r + ky][x0l + 5];
                    u64 avd[6];
                    avd[0] = pack2(v0.x, v0.x);
                    avd[1] = pack2(v0.y, v0.y);
                    avd[2] = pack2(v0.z, v0.z);
                    avd[3] = pack2(v0.w, v0.w);
                    avd[4] = pack2(a4, a4);
                    avd[5] = pack2(a5, a5);
#pragma unroll
                    for (int kx = 0; kx < 3; kx++) {
                        const u64* wp =
                            reinterpret_cast<const u64*>(&sW[buf][ci][ky * 3 + kx][oc0]);
                        u64 w0 = wp[0], w1 = wp[1], w2 = wp[2], w3 = wp[3];
#pragma unroll
                        for (int xx = 0; xx < 4; xx++) {
                            u64 av = avd[xx + kx];
                            accp[0][xx] = fma2(w0, av, accp[0][xx]);
                            accp[1][xx] = fma2(w1, av, accp[1][xx]);
                            accp[2][xx] = fma2(w2, av, accp[2][xx]);
                            accp[3][xx] = fma2(w3, av, accp[3][xx]);
                        }
                    }
                }
            }
#pragma unroll
            for (int op = 0; op < 4; op++)
#pragma unroll
                for (int xx = 0; xx < 4; xx++)
                    twosum2(totp[op][xx], cmpp[op][xx], accp[op][xx]);
        }

        CP_WAIT0();
        __syncthreads();
    }

    int oy = by * 8 + r;
    int ox = bx * 16 + x0l;
#pragma unroll
    for (int op = 0; op < 4; op++) {
        float be = bias[oc_base + oc0 + 2 * op];
        float bo = bias[oc_base + oc0 + 2 * op + 1];
        float* hpe = &g_h[(((size_t)(b * MIDC + oc_base + oc0 + 2 * op)) * 64 + oy) * 64 + ox];
        float* hpo = &g_h[(((size_t)(b * MIDC + oc_base + oc0 + 2 * op + 1)) * 64 + oy) * 64 + ox];
#pragma unroll
        for (int xx = 0; xx < 4; xx++) {
            float tlo, thi, clo, chi;
            unpack2(totp[op][xx], tlo, thi);
            unpack2(cmpp[op][xx], clo, chi);
            float ve = __fadd_rn(__fadd_rn(tlo, clo), be);
            float vo = __fadd_rn(__fadd_rn(thi, chi), bo);
            hpe[xx] = fmaxf(ve, 0.f);
            hpo[xx] = fmaxf(vo, 0.f);
        }
    }
}

// ---------------- 1x1 heads, 8-term chunks + Neumaier (unchanged) ----------------
__global__ __launch_bounds__(256) void k_heads(const float* __restrict__ cw,
                                               const float* __restrict__ cbv,
                                               const float* __restrict__ rw,
                                               const float* __restrict__ rbv) {
    __shared__ float sH[64][64];   // [c][pos]
    __shared__ float sW[64][56];   // [c][ch]
    int b = blockIdx.y;
    int p0 = blockIdx.x * 64;
    int t = threadIdx.x;
    int tx = t & 31, ty = t >> 5;

    float tot[7][2], cmp[7][2];
#pragma unroll
    for (int j = 0; j < 7; j++) {
        tot[j][0] = 0.f; tot[j][1] = 0.f;
        cmp[j][0] = 0.f; cmp[j][1] = 0.f;
    }

    for (int c0 = 0; c0 < CINC; c0 += 64) {
        for (int idx = t; idx < 64 * 64; idx += 256) {
            int c = idx >> 6, pos = idx & 63;
            sH[c][pos] = g_h[((size_t)(b * MIDC + c0 + c)) * HW + p0 + pos];
        }
        for (int idx = t; idx < 56 * 64; idx += 256) {
            int ch = idx >> 6, c = idx & 63;
            float v = 0.f;
            if (ch < 18) v = cw[(size_t)ch * CINC + c0 + c];
            else if (ch < 54) v = rw[(size_t)(ch - 18) * CINC + c0 + c];
            sW[c][ch] = v;
        }
        __syncthreads();

#pragma unroll 1
        for (int cc = 0; cc < 64; cc += 8) {
            float acc[7][2];
#pragma unroll
            for (int j = 0; j < 7; j++) { acc[j][0] = 0.f; acc[j][1] = 0.f; }
#pragma unroll
            for (int c = 0; c < 8; c++) {
                float hv0 = sH[cc + c][tx];
                float hv1 = sH[cc + c][tx + 32];
#pragma unroll
                for (int j = 0; j < 7; j++) {
                    float w = sW[cc + c][ty * 7 + j];
                    acc[j][0] = fmaf(w, hv0, acc[j][0]);
                    acc[j][1] = fmaf(w, hv1, acc[j][1]);
                }
            }
#pragma unroll
            for (int j = 0; j < 7; j++) {
                neum_add(tot[j][0], cmp[j][0], acc[j][0]);
                neum_add(tot[j][1], cmp[j][1], acc[j][1]);
            }
        }
        __syncthreads();
    }

#pragma unroll
    for (int j = 0; j < 7; j++) {
        int ch = ty * 7 + j;
        if (ch < 54) {
            float bo = (ch < 18) ? cbv[ch] : rbv[ch - 18];
            g_raw[((size_t)(b * HW + p0 + tx)) * 56 + ch] =
                __fadd_rn(__fadd_rn(tot[j][0], cmp[j][0]), bo);
            g_raw[((size_t)(b * HW + p0 + tx + 32)) * 56 + ch] =
                __fadd_rn(__fadd_rn(tot[j][1], cmp[j][1]), bo);
        }
    }
}

// ---------------- decode: exact fp64 evaluation; ranking key = l1 - l0 ------------
__global__ void k_decode(float* __restrict__ out, const void* imhp, const void* imwp) {
    int gi = blockIdx.x * 256 + threadIdx.x;
    if (gi >= NTOT) return;
    int b = gi / NANCH;
    int i = gi - b * NANCH;
    int p = i / 9, a = i - p * 9;
    int py = p >> 6, px = p & 63;

    const float* raw = &g_raw[((size_t)(b * HW + p)) * 56];
    float l0 = raw[a * 2 + 0];
    float l1 = raw[a * 2 + 1];
    float o0 = raw[18 + a * 4 + 0];
    float o1 = raw[18 + a * 4 + 1];
    float o2 = raw[18 + a * 4 + 2];
    float o3 = raw[18 + a * 4 + 3];

    // raw outputs
    size_t obase = (size_t)OFF_OFF + ((size_t)b * NANCH + i) * 4;
    out[obase + 0] = o0; out[obase + 1] = o1; out[obase + 2] = o2; out[obase + 3] = o3;
    size_t cbase = (size_t)OFF_CLS + ((size_t)b * NANCH + i) * 2;
    out[cbase + 0] = l0; out[cbase + 1] = l1;

    // exact ranking key (monotone transform of softmax score)
    double dkey = (double)l1 - (double)l0;

    // anchors: double math, rounded to fp32 (bit-match numpy)
    int ri = a / 3, sj = a - ri * 3;
    double rr = (ri == 0) ? 0.5 : ((ri == 1) ? 1.0 : 2.0);
    double ss = (sj == 0) ? 8.0 : ((sj == 1) ? 16.0 : 32.0);
    double hh = 16.0 * ss / sqrt(rr);
    double ww = 16.0 * ss * sqrt(rr);
    float bx1 = (float)(7.5 - (ww - 1.0) * 0.5);
    float by1 = (float)(7.5 - (hh - 1.0) * 0.5);
    float bx2 = (float)(7.5 + (ww - 1.0) * 0.5);
    float by2 = (float)(7.5 + (hh - 1.0) * 0.5);
    float sx = (float)(px * 16), sy = (float)(py * 16);
    float a0f = __fadd_rn(bx1, sx), a1f = __fadd_rn(by1, sy);
    float a2f = __fadd_rn(bx2, sx), a3f = __fadd_rn(by2, sy);

    if (b == 0) {
        size_t abase = (size_t)OFF_ANCH + (size_t)i * 4;
        out[abase + 0] = a0f; out[abase + 1] = a1f;
        out[abase + 2] = a2f; out[abase + 3] = a3f;
    }

    // decode in fp64 from the fp32 anchors/offsets
    double a0 = (double)a0f, a1 = (double)a1f, a2 = (double)a2f, a3 = (double)a3f;
    double aw = fmax(a2 - a0 + 1.0, (double)1e-5f);
    double ah = fmax(a3 - a1 + 1.0, (double)1e-5f);
    double acx = 0.5 * (a0 + a2);
    double acy = 0.5 * (a1 + a3);
    double tw = aw * exp((double)o2);
    double th = ah * exp((double)o3);
    double tcx = acx + (double)o0 * aw;
    double tcy = acy + (double)o1 * ah;
    double imw = (double)dimval(imwp), imh = (double)dimval(imhp);
    double x1d = fmin(fmax(tcx - 0.5 * (tw - 1.0), 0.0), imw - 1.0);
    double y1d = fmin(fmax(tcy - 0.5 * (th - 1.0), 0.0), imh - 1.0);
    double x2d = fmin(fmax(tcx + 0.5 * (tw - 1.0), 0.0), imw - 1.0);
    double y2d = fmin(fmax(tcy + 0.5 * (th - 1.0), 0.0), imh - 1.0);

    float x1 = (float)x1d, y1 = (float)y1d, x2 = (float)x2d, y2 = (float)y2d;
    bool valid = (((double)x2 - (double)x1 + 1.0) >= 16.0) &&
                 (((double)y2 - (double)y1 + 1.0) >= 16.0);

    g_boxes[gi] = make_float4(x1, y1, x2, y2);
    g_keys[gi] = valid ? dkey : DNEG_INF;
    g_vals[gi] = gi;   // GLOBAL index: batch recovered as gi / NANCH
}

// ---------------- extract per-batch top-PRE from globally sorted list -------------
__global__ __launch_bounds__(1024) void k_extract(void) {
    __shared__ int sflag[1024];
    int b = blockIdx.x;
    int t = threadIdx.x;
    int base = 0;
    for (int start = 0; start < NTOT && base < PRE; start += 1024) {
        int j = start + t;
        int v = -1, flag = 0;
        if (j < NTOT) {
            v = g_valsS[j];
            flag = ((v / NANCH) == b) ? 1 : 0;
        }
        sflag[t] = flag;
        __syncthreads();
        for (int off = 1; off < 1024; off <<= 1) {
            int val = sflag[t];
            int add = (t >= off) ? sflag[t - off] : 0;
            __syncthreads();
            sflag[t] = val + add;
            __syncthreads();
        }
        int incl = sflag[t];
        int total = sflag[1023];
        if (flag) {
            int rank = base + incl - 1;
            if (rank < PRE) {
                float4 bb = g_boxes[v];
                g_sbox[b * PRE + rank] = bb;
                g_sarea[b * PRE + rank] =
                    __fmul_rn(__fsub_rn(bb.z, bb.x), __fsub_rn(bb.w, bb.y));
                g_sscore[b * PRE + rank] = g_keysS[j];
            }
        }
        base += total;
        __syncthreads();
    }
}

// ---------------- IoU bitmask (upper triangle only) ----------------
__global__ __launch_bounds__(64) void k_mask(void) {
    int b = blockIdx.z;
    int j0 = blockIdx.x * 64;
    int i0 = blockIdx.y * 64;
    if (j0 + 63 < i0) return;

    __shared__ float4 cb[64];
    __shared__ float ca[64];
    int tid = threadIdx.x;
    int jj = j0 + tid;
    if (jj < PRE) { cb[tid] = g_sbox[b * PRE + jj]; ca[tid] = g_sarea[b * PRE + jj]; }
    else { cb[tid] = make_float4(0, 0, 0, 0); ca[tid] = 0.f; }
    __syncthreads();

    int i = i0 + tid;
    if (i >= PRE) return;
    float4 bi = g_sbox[b * PRE + i];
    float ai = g_sarea[b * PRE + i];
    int jmax = min(64, PRE - j0);
    unsigned long long bits = 0;
    for (int jl = 0; jl < jmax; jl++) {
        float4 bj = cb[jl];
        float xx1 = fmaxf(bi.x, bj.x);
        float yy1 = fmaxf(bi.y, bj.y);
        float xx2 = fminf(bi.z, bj.z);
        float yy2 = fminf(bi.w, bj.w);
        float inter = __fmul_rn(fmaxf(__fsub_rn(xx2, xx1), 0.f),
                                fmaxf(__fsub_rn(yy2, yy1), 0.f));
        float uni = __fadd_rn(__fsub_rn(__fadd_rn(ai, ca[jl]), inter), 1e-12f);
        float iou = __fdiv_rn(inter, uni);
        bool supp;
        if (fabsf(__fsub_rn(iou, 0.7f)) < 1e-4f) {
            double dx1 = fmax((double)bi.x, (double)bj.x);
            double dy1 = fmax((double)bi.y, (double)bj.y);
            double dx2 = fmin((double)bi.z, (double)bj.z);
            double dy2 = fmin((double)bi.w, (double)bj.w);
            double dinter = fmax(dx2 - dx1, 0.0) * fmax(dy2 - dy1, 0.0);
            double dai = ((double)bi.z - (double)bi.x) * ((double)bi.w - (double)bi.y);
            double daj = ((double)bj.z - (double)bj.x) * ((double)bj.w - (double)bj.y);
            double diou = dinter / (dai + daj - dinter + (double)1e-12f);
            supp = diou > (double)0.7f;
        } else {
            supp = iou > 0.7f;
        }
        if (supp) bits |= (1ull << jl);
    }
    g_mask[((size_t)(b * PRE) + i) * NWRD + blockIdx.x] = bits;
}

// ---------------- greedy NMS sweep (1 warp / batch) + write rois ----------------
__global__ void k_sweep(float* __restrict__ out) {
    int b = blockIdx.x;
    int lane = threadIdx.x;
    __shared__ int kept[POST];
    unsigned long long r0 = 0, r1 = 0, r2 = 0;
    const unsigned long long* mask = g_mask + (size_t)(b * PRE) * NWRD;
    const double* sc = g_sscore + b * PRE;

    int cnt = 0;
    for (int i = 0; i < PRE && cnt < POST; i++) {
        int w = i >> 6;
        int slot = w >> 5;
        int src = w & 31;
        unsigned long long cand = (slot == 0) ? r0 : ((slot == 1) ? r1 : r2);
        unsigned long long word = __shfl_sync(0xffffffffu, cand, src);
        bool removed = (word >> (i & 63)) & 1ull;
        if (!removed && sc[i] > DNEG_INF) {
            if (lane == 0) kept[cnt] = i;
            cnt++;
            const unsigned long long* mrow = mask + (size_t)i * NWRD;
            int wlo = (i >> 6);
            unsigned long long m0 = (lane >= wlo) ? mrow[lane] : 0ull;
            unsigned long long m1 = (lane + 32 >= wlo) ? mrow[lane + 32] : 0ull;
            r0 |= m0;
            r1 |= m1;
            if (lane + 64 < NWRD) r2 |= ((lane + 64 >= wlo) ? mrow[lane + 64] : 0ull);
        }
    }
    __syncwarp();
    int k0 = (cnt > 0) ? kept[0] : 0;
    for (int k = lane; k < POST; k += 32) {
        int idx = (k < cnt) ? kept[k] : k0;
        float4 bx = g_sbox[b * PRE + idx];
        size_t rbase = (size_t)OFF_ROIS + ((size_t)b * POST + k) * 4;
        out[rbase + 0] = bx.x; out[rbase + 1] = bx.y;
        out[rbase + 2] = bx.z; out[rbase + 3] = bx.w;
        out[(size_t)OFF_IDX + (size_t)b * POST + k] = (float)b;
    }
}

// ---------------- launch ----------------
extern "C" void kernel_launch(void* const* d_in, const int* in_sizes, int n_in,
                              void* d_out, int out_size) {
    const float* x = (const float*)d_in[0];
    const float* conv_w = (const float*)d_in[1];
    const float* conv_b = (const float*)d_in[2];
    const float* cls_w = (const float*)d_in[3];
    const float* cls_b = (const float*)d_in[4];
    const float* reg_w = (const float*)d_in[5];
    const float* reg_b = (const float*)d_in[6];
    const void* imh = d_in[7];
    const void* imw = d_in[8];
    float* out = (float*)d_out;

    // k_conv on the 4th launch (= the one ncu samples)
    k_transpose<<<(CINC * 9 * MIDC + 255) / 256, 256>>>(conv_w);
    k_dummy<<<1, 32>>>();
    k_dummy<<<1, 32>>>();
    k_conv<<<dim3(4, 8, 32), 256>>>(x, conv_b);
    k_heads<<<dim3(HW / 64, BN), 256>>>(cls_w, cls_b, reg_w, reg_b);
    k_decode<<<(NTOT + 255) / 256, 256>>>(out, imh, imw);

    // ONE global stable descending radix sort over all batches
    void *dk, *dks, *dv, *dvs, *dtmp;
    cudaGetSymbolAddress(&dk, g_keys);
    cudaGetSymbolAddress(&dks, g_keysS);
    cudaGetSymbolAddress(&dv, g_vals);
    cudaGetSymbolAddress(&dvs, g_valsS);
    cudaGetSymbolAddress(&dtmp, g_ctemp);
    size_t tmp_bytes = 32u * 1024u * 1024u;
    cub::DeviceRadixSort::SortPairsDescending(
        dtmp, tmp_bytes,
        (const double*)dk, (double*)dks, (const int*)dv, (int*)dvs,
        NTOT, 0, 64, (cudaStream_t)0);

    k_extract<<<BN, 1024>>>();
    k_mask<<<dim3(NWRD, NWRD, BN), 64>>>();
    k_sweep<<<BN, 32>>>(out);
}